// round 2
// baseline (speedup 1.0000x reference)
#include <cuda_runtime.h>
#include <math.h>

// ---------------- problem constants ----------------
#define BSZ 1024
#define NN  7
#define DD  1024
#define MROWS (BSZ*NN)        // 7168

// output layout (tuple flattened in order):
// fused (B*D), updated (B*N*D), imp (B*N), attn (B*N*N), phys (1), align (1)
#define OFF_FUSED 0
#define OFF_UPD   (BSZ*DD)                    // 1048576
#define OFF_IMP   (OFF_UPD + BSZ*NN*DD)       // 8388608
#define OFF_ATTN  (OFF_IMP + BSZ*NN)          // 8395776
#define OFF_PHYS  (OFF_ATTN + BSZ*NN*NN)      // 8445952
#define OFF_ALIGN (OFF_PHYS + 1)              // 8445953

// ---------------- scratch (allocation-free: __device__ globals) ----------------
__device__ float pg_q  [MROWS*DD];
__device__ float pg_k  [MROWS*DD];
__device__ float pg_v  [MROWS*DD];
__device__ float pg_la [MROWS*DD];
__device__ float pg_rb [MROWS*DD];
__device__ float pg_cc [BSZ*DD];
__device__ float pg_msg[MROWS*DD];
__device__ float pg_h1 [MROWS*DD];
__device__ float pg_h2 [MROWS*DD];
__device__ float pg_gq [MROWS*DD];
__device__ float pg_part[BSZ*3];

// ADJ matrix
__constant__ float c_adj[49] = {
    1,1,0,0,1,1,1,
    1,1,1,1,1,1,1,
    0,1,1,0,1,0,1,
    0,1,0,1,1,1,1,
    1,1,1,1,1,1,1,
    1,1,0,1,1,1,1,
    1,1,1,1,1,1,1};

__device__ __forceinline__ float gelu_f(float x) {
    return 0.5f * x * (1.0f + erff(x * 0.70710678118654752440f));
}

// ---------------- generic SGEMM: C[M,1024] = concatA[M,K] @ W[K,1024] (+bias)(+gelu|+res) ----------------
#define EPI_NONE 0
#define EPI_GELU 1
#define EPI_RES  2

__global__ __launch_bounds__(256, 2)
void sgemm_kernel(const float* __restrict__ A0, int lda0,
                  const float* __restrict__ A1, int lda1, int ksplit,
                  const float* __restrict__ W,
                  const float* __restrict__ bias,
                  const float* __restrict__ R,
                  float* __restrict__ C,
                  int K, int epi)
{
    __shared__ float As[8][128];
    __shared__ float Bs[8][128];
    const int tid = threadIdx.x;
    const int ty = tid >> 4, tx = tid & 15;
    const int m0 = blockIdx.y * 128;
    const int n0 = blockIdx.x * 128;

    float acc[8][8];
#pragma unroll
    for (int i = 0; i < 8; i++)
#pragma unroll
        for (int j = 0; j < 8; j++) acc[i][j] = 0.f;

    const int ar  = tid >> 1;          // 0..127 row within A tile
    const int akq = (tid & 1) * 4;     // 0 or 4
    const int wkr = tid >> 5;          // 0..7
    const int wnc = (tid & 31) * 4;    // 0..124

    for (int k0 = 0; k0 < K; k0 += 8) {
        const int kc = k0 + akq;
        const float* ap;
        if (kc < ksplit) ap = A0 + (size_t)(m0 + ar) * lda0 + kc;
        else             ap = A1 + (size_t)(m0 + ar) * lda1 + (kc - ksplit);
        float4 av = *(const float4*)ap;
        As[akq + 0][ar] = av.x; As[akq + 1][ar] = av.y;
        As[akq + 2][ar] = av.z; As[akq + 3][ar] = av.w;

        float4 wv = *(const float4*)(W + (size_t)(k0 + wkr) * 1024 + n0 + wnc);
        *(float4*)&Bs[wkr][wnc] = wv;
        __syncthreads();

#pragma unroll
        for (int kk = 0; kk < 8; kk++) {
            float a[8], bb[8];
#pragma unroll
            for (int i = 0; i < 8; i++) a[i]  = As[kk][ty * 8 + i];
#pragma unroll
            for (int j = 0; j < 8; j++) bb[j] = Bs[kk][tx * 8 + j];
#pragma unroll
            for (int i = 0; i < 8; i++)
#pragma unroll
                for (int j = 0; j < 8; j++)
                    acc[i][j] = fmaf(a[i], bb[j], acc[i][j]);
        }
        __syncthreads();
    }

    float bvv[8];
#pragma unroll
    for (int j = 0; j < 8; j++) bvv[j] = bias ? bias[n0 + tx * 8 + j] : 0.f;

#pragma unroll
    for (int i = 0; i < 8; i++) {
        const int row = m0 + ty * 8 + i;
        float* crow = C + (size_t)row * 1024 + n0 + tx * 8;
        const float* rrow = (epi == EPI_RES) ? (R + (size_t)row * 1024 + n0 + tx * 8) : nullptr;
#pragma unroll
        for (int j = 0; j < 8; j++) {
            float cv = acc[i][j] + bvv[j];
            if (epi == EPI_GELU)      cv = gelu_f(cv);
            else if (epi == EPI_RES)  cv += rrow[j];
            crow[j] = cv;
        }
    }
}

// ---------------- fused attention (per batch): qk logits + edge MLP + mask + softmax + messages ----------------
__global__ void attn_kernel(const float* __restrict__ q, const float* __restrict__ k,
                            const float* __restrict__ v, const float* __restrict__ la,
                            const float* __restrict__ rb, const float* __restrict__ cc,
                            const float* __restrict__ be1, const float* __restrict__ We2,
                            const float* __restrict__ be2,
                            float* __restrict__ attn_out, float* __restrict__ msg)
{
    const int b = blockIdx.x;
    extern __shared__ float sm[];
    float* sq  = sm;               // 7*1024
    float* sk  = sq  + NN * DD;
    float* sv  = sk  + NN * DD;
    float* sla = sv  + NN * DD;
    float* srb = sla + NN * DD;
    float* scc = srb + NN * DD;    // 1024
    float* sbe = scc + DD;         // 1024
    float* sw2 = sbe + DD;         // 1024
    __shared__ float s_logits[49];
    __shared__ float s_attn[49];

    const int tid = threadIdx.x;
    const size_t base = (size_t)b * NN * DD;
    for (int i = tid; i < NN * DD; i += 256) {
        sq[i]  = q[base + i];
        sk[i]  = k[base + i];
        sv[i]  = v[base + i];
        sla[i] = la[base + i];
        srb[i] = rb[base + i];
    }
    for (int i = tid; i < DD; i += 256) {
        scc[i] = cc[(size_t)b * DD + i];
        sbe[i] = be1[i];
        sw2[i] = We2[i];
    }
    __syncthreads();

    const int warp = tid >> 5, lane = tid & 31;
    const float be2v = be2[0];
    for (int p = warp; p < 49; p += 8) {
        const int n = p / 7, m = p % 7;
        float aqk = 0.f, ae = 0.f;
        for (int d = lane; d < DD; d += 32) {
            aqk = fmaf(sq[n * DD + d], sk[m * DD + d], aqk);
            float x = sla[n * DD + d] + srb[m * DD + d] + scc[d] + sbe[d];
            ae = fmaf(gelu_f(x), sw2[d], ae);
        }
#pragma unroll
        for (int o = 16; o; o >>= 1) {
            aqk += __shfl_xor_sync(0xffffffffu, aqk, o);
            ae  += __shfl_xor_sync(0xffffffffu, ae,  o);
        }
        if (lane == 0)
            s_logits[p] = aqk * (1.0f / 32.0f) + ae + be2v + (c_adj[p] - 1.0f) * 10000.0f;
    }
    __syncthreads();

    if (tid < 7) {
        const int n = tid;
        float mx = -1e30f;
#pragma unroll
        for (int m = 0; m < 7; m++) mx = fmaxf(mx, s_logits[n * 7 + m]);
        float s = 0.f;
        float e[7];
#pragma unroll
        for (int m = 0; m < 7; m++) { e[m] = expf(s_logits[n * 7 + m] - mx); s += e[m]; }
        const float inv = 1.0f / s;
#pragma unroll
        for (int m = 0; m < 7; m++) {
            const float a = e[m] * inv;
            s_attn[n * 7 + m] = a;
            attn_out[(size_t)b * 49 + n * 7 + m] = a;
        }
    }
    __syncthreads();

    for (int i = tid; i < NN * DD; i += 256) {
        const int n = i >> 10, d = i & 1023;
        float s = 0.f;
#pragma unroll
        for (int m = 0; m < 7; m++) s = fmaf(s_attn[n * 7 + m], sv[m * DD + d], s);
        msg[base + i] = s;
    }
}

// ---------------- gq broadcast copy ----------------
__global__ void gq_copy_kernel(const float* __restrict__ upd, float* __restrict__ gq)
{
    const int idx = blockIdx.x * 256 + threadIdx.x;
    const int r = idx >> 10;
    const int d = idx & 1023;
    const int b = r / 7;
    gq[idx] = upd[(size_t)(b * 7 + 6) * 1024 + d];
}

// ---------------- per-batch finalize: imp logits/softmax/cap, fused, loss partials ----------------
__global__ void final_kernel(const float* __restrict__ upd, const float* __restrict__ h2,
                             const float* __restrict__ Wi2, const float* __restrict__ bi2,
                             float* __restrict__ out_fused, float* __restrict__ out_imp,
                             float* __restrict__ part)
{
    const int b = blockIdx.x;
    __shared__ float su[NN * DD];
    __shared__ float sf[DD];
    __shared__ float s_dot[49];
    __shared__ float s_implog[7];
    __shared__ float s_imp[8];
    __shared__ float s_dotf[7];
    __shared__ float s_fn2;

    const int tid = threadIdx.x, warp = tid >> 5, lane = tid & 31;
    const size_t base = (size_t)b * NN * DD;
    for (int i = tid; i < NN * DD; i += 256) su[i] = upd[base + i];
    __syncthreads();

    // pairwise dots (diagonal = squared norms)
    for (int p = warp; p < 49; p += 8) {
        const int n = p / 7, m = p % 7;
        float s = 0.f;
        for (int d = lane; d < DD; d += 32) s = fmaf(su[n * DD + d], su[m * DD + d], s);
#pragma unroll
        for (int o = 16; o; o >>= 1) s += __shfl_xor_sync(0xffffffffu, s, o);
        if (lane == 0) s_dot[p] = s;
    }
    // importance logits
    if (warp < 7) {
        float s = 0.f;
        for (int d = lane; d < DD; d += 32) s = fmaf(h2[base + warp * DD + d], Wi2[d], s);
#pragma unroll
        for (int o = 16; o; o >>= 1) s += __shfl_xor_sync(0xffffffffu, s, o);
        if (lane == 0) s_implog[warp] = s + bi2[0];
    }
    __syncthreads();

    if (tid == 0) {
        float mx = -1e30f;
#pragma unroll
        for (int n = 0; n < 7; n++) mx = fmaxf(mx, s_implog[n]);
        float e[7], sum = 0.f;
#pragma unroll
        for (int n = 0; n < 7; n++) { e[n] = expf(s_implog[n] - mx); sum += e[n]; }
        float imp[7];
#pragma unroll
        for (int n = 0; n < 7; n++) imp[n] = e[n] / sum;
        const float cap[7] = {1.f, 1.f, 1.f, 0.26f, 1.f, 1.f, 0.24f};
        const float fre[7] = {1.f, 1.f, 1.f, 0.f, 1.f, 1.f, 0.f};
        float capped[7], csum = 0.f, fmass = 0.f;
#pragma unroll
        for (int n = 0; n < 7; n++) {
            capped[n] = fminf(imp[n], cap[n]);
            csum += capped[n];
            fmass += imp[n] * fre[n];
        }
        const float residual = fmaxf(1.0f - csum, 0.0f);
        float redis[7], rsum = 0.f;
#pragma unroll
        for (int n = 0; n < 7; n++) {
            const float fs = (fmass > 1e-6f) ? imp[n] * fre[n] / fmaxf(fmass, 1e-6f)
                                             : fre[n] * 0.2f;
            redis[n] = capped[n] + fs * residual;
            rsum += redis[n];
        }
        const float inv = 1.0f / fmaxf(rsum, 1e-6f);
#pragma unroll
        for (int n = 0; n < 7; n++) {
            s_imp[n] = redis[n] * inv;
            out_imp[b * 7 + n] = s_imp[n];
        }
    }
    __syncthreads();

    for (int d = tid; d < DD; d += 256) {
        float f = 0.f;
#pragma unroll
        for (int n = 0; n < 7; n++) f = fmaf(s_imp[n], su[n * DD + d], f);
        sf[d] = f;
        out_fused[(size_t)b * DD + d] = f;
    }
    __syncthreads();

    if (warp < 7) {
        float s = 0.f;
        for (int d = lane; d < DD; d += 32) s = fmaf(su[warp * DD + d], sf[d], s);
#pragma unroll
        for (int o = 16; o; o >>= 1) s += __shfl_xor_sync(0xffffffffu, s, o);
        if (lane == 0) s_dotf[warp] = s;
    } else {
        float s = 0.f;
        for (int d = lane; d < DD; d += 32) s = fmaf(sf[d], sf[d], s);
#pragma unroll
        for (int o = 16; o; o >>= 1) s += __shfl_xor_sync(0xffffffffu, s, o);
        if (lane == 0) s_fn2 = s;
    }
    __syncthreads();

    if (tid == 0) {
        float norm[7];
#pragma unroll
        for (int n = 0; n < 7; n++) norm[n] = sqrtf(s_dot[n * 7 + n]);
        const float fnorm = sqrtf(s_fn2);
        float edge = 0.f, non = 0.f, align = 0.f;
#pragma unroll
        for (int n = 0; n < 7; n++) {
#pragma unroll
            for (int m = 0; m < 7; m++) {
                const float cosv = s_dot[n * 7 + m] / fmaxf(norm[n] * norm[m], 1e-8f);
                const float adj = c_adj[n * 7 + m];
                edge += (1.0f - cosv) * adj;
                if (n != m) non += fmaxf(cosv - 0.35f, 0.0f) * (1.0f - adj);
            }
            align += 1.0f - s_dotf[n] / (fmaxf(norm[n], 1e-12f) * fmaxf(fnorm, 1e-12f));
        }
        part[b * 3 + 0] = edge;
        part[b * 3 + 1] = non;
        part[b * 3 + 2] = align;
    }
}

// ---------------- deterministic loss reduction ----------------
__global__ void loss_reduce_kernel(const float* __restrict__ part, float* __restrict__ out)
{
    __shared__ float se[256], sn[256], sa[256];
    const int t = threadIdx.x;
    float e = 0.f, n = 0.f, a = 0.f;
    for (int i = t; i < BSZ; i += 256) {
        e += part[i * 3 + 0];
        n += part[i * 3 + 1];
        a += part[i * 3 + 2];
    }
    se[t] = e; sn[t] = n; sa[t] = a;
    __syncthreads();
    for (int s = 128; s; s >>= 1) {
        if (t < s) { se[t] += se[t + s]; sn[t] += sn[t + s]; sa[t] += sa[t + s]; }
        __syncthreads();
    }
    if (t == 0) {
        out[OFF_PHYS]  = se[0] / 41.0f + 0.5f * (sn[0] / 8.0f);
        out[OFF_ALIGN] = sa[0] / 7168.0f;
    }
}

// ---------------- host launch ----------------
extern "C" void kernel_launch(void* const* d_in, const int* in_sizes, int n_in,
                              void* d_out, int out_size)
{
    (void)in_sizes; (void)n_in; (void)out_size;
    const float* nodes = (const float*)d_in[0];
    const float* Wq  = (const float*)d_in[1];  const float* bq  = (const float*)d_in[2];
    const float* Wk  = (const float*)d_in[3];  const float* bk  = (const float*)d_in[4];
    const float* Wv  = (const float*)d_in[5];  const float* bv  = (const float*)d_in[6];
    const float* We1 = (const float*)d_in[7];  const float* be1 = (const float*)d_in[8];
    const float* We2 = (const float*)d_in[9];  const float* be2 = (const float*)d_in[10];
    const float* Wu1 = (const float*)d_in[11]; const float* bu1 = (const float*)d_in[12];
    const float* Wu2 = (const float*)d_in[13]; const float* bu2 = (const float*)d_in[14];
    const float* Wi1 = (const float*)d_in[15]; const float* bi1 = (const float*)d_in[16];
    const float* Wi2 = (const float*)d_in[17]; const float* bi2 = (const float*)d_in[18];
    float* out = (float*)d_out;

    float *pq, *pk, *pv, *pla, *prb, *pcc, *pmsg, *ph1, *ph2, *pgq, *ppart;
    cudaGetSymbolAddress((void**)&pq,   pg_q);
    cudaGetSymbolAddress((void**)&pk,   pg_k);
    cudaGetSymbolAddress((void**)&pv,   pg_v);
    cudaGetSymbolAddress((void**)&pla,  pg_la);
    cudaGetSymbolAddress((void**)&prb,  pg_rb);
    cudaGetSymbolAddress((void**)&pcc,  pg_cc);
    cudaGetSymbolAddress((void**)&pmsg, pg_msg);
    cudaGetSymbolAddress((void**)&ph1,  pg_h1);
    cudaGetSymbolAddress((void**)&ph2,  pg_h2);
    cudaGetSymbolAddress((void**)&pgq,  pg_gq);
    cudaGetSymbolAddress((void**)&ppart, pg_part);

    const dim3 blk(256);
    const dim3 grid_big(8, MROWS / 128);   // (8, 56)
    const dim3 grid_cc(8, BSZ / 128);      // (8, 8)
    const int BIGK = 1 << 30;

    // q, k, v
    sgemm_kernel<<<grid_big, blk>>>(nodes, DD, nullptr, 0, BIGK, Wq, bq, nullptr, pq, DD, EPI_NONE);
    sgemm_kernel<<<grid_big, blk>>>(nodes, DD, nullptr, 0, BIGK, Wk, bk, nullptr, pk, DD, EPI_NONE);
    sgemm_kernel<<<grid_big, blk>>>(nodes, DD, nullptr, 0, BIGK, Wv, bv, nullptr, pv, DD, EPI_NONE);
    // la = nodes@We1[:D], rb = nodes@We1[D:2D], cc = nodes[:,-1]@We1[2D:]
    sgemm_kernel<<<grid_big, blk>>>(nodes, DD, nullptr, 0, BIGK, We1,            nullptr, nullptr, pla, DD, EPI_NONE);
    sgemm_kernel<<<grid_big, blk>>>(nodes, DD, nullptr, 0, BIGK, We1 + DD * DD,  nullptr, nullptr, prb, DD, EPI_NONE);
    sgemm_kernel<<<grid_cc,  blk>>>(nodes + 6 * DD, NN * DD, nullptr, 0, BIGK, We1 + 2 * DD * DD, nullptr, nullptr, pcc, DD, EPI_NONE);

    // fused attention + edge MLP + messages
    const int attn_smem = (5 * NN * DD + 3 * DD) * (int)sizeof(float);  // 155648
    cudaFuncSetAttribute(attn_kernel, cudaFuncAttributeMaxDynamicSharedMemorySize, attn_smem);
    attn_kernel<<<BSZ, blk, attn_smem>>>(pq, pk, pv, pla, prb, pcc, be1, We2, be2,
                                         out + OFF_ATTN, pmsg);

    // h1 = gelu(concat(nodes, msg) @ Wu1 + bu1)
    sgemm_kernel<<<grid_big, blk>>>(nodes, DD, pmsg, DD, DD, Wu1, bu1, nullptr, ph1, 2 * DD, EPI_GELU);
    // updated = h1 @ Wu2 + bu2 + nodes   -> written straight to output
    sgemm_kernel<<<grid_big, blk>>>(ph1, DD, nullptr, 0, BIGK, Wu2, bu2, nodes, out + OFF_UPD, DD, EPI_RES);

    // gq broadcast
    gq_copy_kernel<<<(MROWS * DD) / 256, blk>>>(out + OFF_UPD, pgq);
    // h2 = gelu(concat(updated, gq) @ Wi1 + bi1)
    sgemm_kernel<<<grid_big, blk>>>(out + OFF_UPD, DD, pgq, DD, DD, Wi1, bi1, nullptr, ph2, 2 * DD, EPI_GELU);

    // finalize: imp, fused, loss partials
    final_kernel<<<BSZ, blk>>>(out + OFF_UPD, ph2, Wi2, bi2, out + OFF_FUSED, out + OFF_IMP, ppart);
    loss_reduce_kernel<<<1, blk>>>(ppart, out);
}